// round 12
// baseline (speedup 1.0000x reference)
#include <cuda_runtime.h>
#include <cuda_fp16.h>
#include <cstdint>
#include <cstddef>

#define NE 2048
#define NH 16
#define HD 128
#define SB 2048
#define NB 2
#define MT 4096     // NB*SB
#define NQKV 2304   // 2048 (Q) + 128 (K) + 128 (V)

// ---------------- scratch (__device__ globals; no allocs) ------------------
__device__ __half g_xh   [MT * NE];
__device__ __half g_qkvh [MT * NQKV];      // fused Q|K|V, row stride 2304
__device__ __half g_aoh  [MT * NE];
__device__ __half g_wqkvh[NQKV * NE];
__device__ __half g_woh  [NE * NE];
__device__ float  g_bqkv [NQKV];

// ---------------- PTX helpers (sm_80-safe; no 'a' features) ----------------
#define CP16(sa, g)  asm volatile("cp.async.cg.shared.global [%0], [%1], 16;" :: "r"(sa), "l"(g))
#define CP_COMMIT()  asm volatile("cp.async.commit_group;" ::: "memory")
#define CP_WAIT1()   asm volatile("cp.async.wait_group 1;" ::: "memory")
#define CP_WAIT0()   asm volatile("cp.async.wait_group 0;" ::: "memory")

#define LDSM_X4(r0,r1,r2,r3, addr) \
    asm volatile("ldmatrix.sync.aligned.m8n8.x4.shared.b16 {%0,%1,%2,%3}, [%4];" \
        : "=r"(r0),"=r"(r1),"=r"(r2),"=r"(r3) : "r"(addr))
#define LDSM_X4T(r0,r1,r2,r3, addr) \
    asm volatile("ldmatrix.sync.aligned.m8n8.x4.trans.shared.b16 {%0,%1,%2,%3}, [%4];" \
        : "=r"(r0),"=r"(r1),"=r"(r2),"=r"(r3) : "r"(addr))
#define LDSM_X2T(r0,r1, addr) \
    asm volatile("ldmatrix.sync.aligned.m8n8.x2.trans.shared.b16 {%0,%1}, [%2];" \
        : "=r"(r0),"=r"(r1) : "r"(addr))
#define MMA16816(c0,c1,c2,c3, a0,a1,a2,a3, b0,b1) \
    asm volatile("mma.sync.aligned.m16n8k16.row.col.f32.f16.f16.f32 " \
        "{%0,%1,%2,%3}, {%4,%5,%6,%7}, {%8,%9}, {%0,%1,%2,%3};" \
        : "+f"(c0),"+f"(c1),"+f"(c2),"+f"(c3) \
        : "r"(a0),"r"(a1),"r"(a2),"r"(a3),"r"(b0),"r"(b1))
#define EX2H2(x) asm volatile("ex2.approx.f16x2 %0, %0;" : "+r"(x))

__device__ __forceinline__ uint32_t smem_u32(const void* p) {
    return (uint32_t)__cvta_generic_to_shared(p);
}
__device__ __forceinline__ uint32_t pack_h2(float a, float b) {
    __half2 h = __floats2half2_rn(a, b);
    return *(uint32_t*)&h;
}
__device__ __forceinline__ float ex2f(float x) {
    float y;
    asm("ex2.approx.ftz.f32 %0, %1;" : "=f"(y) : "f"(x));
    return y;
}

// ---------------- fused conversion kernels ----------------------------------
__global__ void __launch_bounds__(256)
conv_wb(const float* __restrict__ Wq, const float* __restrict__ Wk,
        const float* __restrict__ Wv, const float* __restrict__ Wo,
        const float* __restrict__ bq, const float* __restrict__ bk,
        const float* __restrict__ bv,
        __half* __restrict__ wqkvh, __half* __restrict__ woh,
        float* __restrict__ bqkv, float scale)
{
    constexpr int S0 = NE * NE;
    constexpr int S1 = S0 + HD * NE;
    constexpr int S2 = S1 + HD * NE;
    constexpr int S3 = S2 + NE * NE;
    const int i = (blockIdx.x * 256 + threadIdx.x) * 4;
    if (i < S0) {
        float4 v = *(const float4*)(Wq + i);
        __half2* o = (__half2*)(wqkvh + i);
        o[0] = __floats2half2_rn(v.x * scale, v.y * scale);
        o[1] = __floats2half2_rn(v.z * scale, v.w * scale);
    } else if (i < S1) {
        const int j = i - S0;
        float4 v = *(const float4*)(Wk + j);
        __half2* o = (__half2*)(wqkvh + NE * NE + j);
        o[0] = __floats2half2_rn(v.x, v.y);
        o[1] = __floats2half2_rn(v.z, v.w);
    } else if (i < S2) {
        const int j = i - S1;
        float4 v = *(const float4*)(Wv + j);
        __half2* o = (__half2*)(wqkvh + (NE + HD) * NE + j);
        o[0] = __floats2half2_rn(v.x, v.y);
        o[1] = __floats2half2_rn(v.z, v.w);
    } else if (i < S3) {
        const int j = i - S2;
        float4 v = *(const float4*)(Wo + j);
        __half2* o = (__half2*)(woh + j);
        o[0] = __floats2half2_rn(v.x, v.y);
        o[1] = __floats2half2_rn(v.z, v.w);
    } else {
        #pragma unroll
        for (int u = 0; u < 4; u++) {
            const int bidx = (i - S3) + u;
            if (bidx < NE)            bqkv[bidx] = bq[bidx] * scale;
            else if (bidx < NE + HD)  bqkv[bidx] = bk[bidx - NE];
            else if (bidx < NQKV)     bqkv[bidx] = bv[bidx - NE - HD];
        }
    }
}

__global__ void __launch_bounds__(256)
conv_x(const float* __restrict__ in, __half* __restrict__ out, int n)
{
    int i = (blockIdx.x * 256 + threadIdx.x) * 4;
    if (i < n) {
        float4 v = *(const float4*)(in + i);
        __half2* o = (__half2*)(out + i);
        o[0] = __floats2half2_rn(v.x, v.y);
        o[1] = __floats2half2_rn(v.z, v.w);
    }
}

// ---------------------------------------------------------------------------
// HMMA GEMM: 128x128 CTA tile, 4 warps, warp tile 64x64, BK=32,
// 3-stage cp.async, 2 CTAs/SM. (R7/R9-validated)
// ---------------------------------------------------------------------------
#define PAD 40
#define STG (128 * PAD)
#define AOFF(st) ((st) * STG * 2)
#define BOFF(st) (3 * STG * 2 + (st) * STG * 2)
#define GEMM_SMEM (6 * STG * 2)

template<typename OutT>
__global__ void __launch_bounds__(128, 2)
gemm_hmma64(const __half* __restrict__ A, const __half* __restrict__ B,
            const float* __restrict__ bias, OutT* __restrict__ C,
            int M, int N, int K)
{
    extern __shared__ __half sh[];
    const uint32_t smb = smem_u32(sh);

    const int tid  = threadIdx.x;
    const int wid  = tid >> 5;
    const int lane = tid & 31;
    const int bm = blockIdx.y * 128;
    const int bn = blockIdx.x * 128;
    const int m0 = (wid >> 1) * 64;
    const int n0 = (wid & 1) * 64;

    const int lrow = tid >> 2;
    const int lch  = tid & 3;

    float c[4][8][4];
    #pragma unroll
    for (int mt = 0; mt < 4; mt++)
        #pragma unroll
        for (int nt = 0; nt < 8; nt++)
            #pragma unroll
            for (int r = 0; r < 4; r++) c[mt][nt][r] = 0.f;

    const __half* Ab = A + (size_t)bm * K;
    const __half* Bb = B + (size_t)bn * K;
    const int nk = K / 32;

    auto load_stage = [&](int st, int k0) {
        #pragma unroll
        for (int r = 0; r < 4; r++) {
            const int row = lrow + r * 32;
            const uint32_t so = (uint32_t)(row * PAD + lch * 8) * 2;
            CP16(smb + AOFF(st) + so, Ab + (size_t)row * K + k0 + lch * 8);
            CP16(smb + BOFF(st) + so, Bb + (size_t)row * K + k0 + lch * 8);
        }
    };

    load_stage(0, 0);  CP_COMMIT();
    load_stage(1, 32); CP_COMMIT();

    const int a_r = lane & 15, a_c = (lane >> 4) * 8;
    const int b_row = ((lane >> 4) << 3) + (lane & 7);
    const int b_col = ((lane >> 3) & 1) * 8;

    for (int i = 0; i < nk; i++) {
        CP_WAIT1();
        __syncthreads();
        if (i + 2 < nk) load_stage((i + 2) % 3, (i + 2) * 32);
        CP_COMMIT();

        const int st = i % 3;
        #pragma unroll
        for (int ks = 0; ks < 2; ks++) {
            uint32_t a[4][4], b[8][2];
            #pragma unroll
            for (int mt = 0; mt < 4; mt++) {
                const uint32_t addr = smb + AOFF(st) +
                    (uint32_t)((m0 + mt * 16 + a_r) * PAD + ks * 16 + a_c) * 2;
                LDSM_X4(a[mt][0], a[mt][1], a[mt][2], a[mt][3], addr);
            }
            #pragma unroll
            for (int np = 0; np < 4; np++) {
                const uint32_t addr = smb + BOFF(st) +
                    (uint32_t)((n0 + np * 16 + b_row) * PAD + ks * 16 + b_col) * 2;
                LDSM_X4(b[2*np][0], b[2*np][1], b[2*np+1][0], b[2*np+1][1], addr);
            }
            #pragma unroll
            for (int mt = 0; mt < 4; mt++)
                #pragma unroll
                for (int nt = 0; nt < 8; nt++)
                    MMA16816(c[mt][nt][0], c[mt][nt][1], c[mt][nt][2], c[mt][nt][3],
                             a[mt][0], a[mt][1], a[mt][2], a[mt][3],
                             b[nt][0], b[nt][1]);
        }
        __syncthreads();
    }

    const int tr  = lane >> 2;
    const int tc2 = (lane & 3) * 2;
    #pragma unroll
    for (int mt = 0; mt < 4; mt++) {
        const int r0 = bm + m0 + mt * 16 + tr;
        #pragma unroll
        for (int nt = 0; nt < 8; nt++) {
            const int cc = bn + n0 + nt * 8 + tc2;
            const float bx = bias[cc], by = bias[cc + 1];
            if constexpr (sizeof(OutT) == 4) {
                *(float2*)&C[(size_t)r0 * N + cc] =
                    make_float2(c[mt][nt][0] + bx, c[mt][nt][1] + by);
                *(float2*)&C[(size_t)(r0 + 8) * N + cc] =
                    make_float2(c[mt][nt][2] + bx, c[mt][nt][3] + by);
            } else {
                *(__half2*)&C[(size_t)r0 * N + cc] =
                    __floats2half2_rn(c[mt][nt][0] + bx, c[mt][nt][1] + by);
                *(__half2*)&C[(size_t)(r0 + 8) * N + cc] =
                    __floats2half2_rn(c[mt][nt][2] + bx, c[mt][nt][3] + by);
            }
        }
    }
}

// ---------------------------------------------------------------------------
// HMMA MQA flash attention v4: 128 q-rows/CTA, 4 warps x 32 rows, KV tile
// narrowed 64 -> 32 cols: s[2][4][4] + pa[2][2][4] cuts ~48 live registers
// (R11 profile showed regs=255 = spilling), same low port traffic.
// SMEM halves: Q[128][136] @0; KV buf = K[32][136] + V[32][136] (x2 buffers).
// ---------------------------------------------------------------------------
#define QSM   17408u                          // Q halves
#define KVT   32                              // kv tile rows
#define KHALF 4352u                           // one K (or V) tile halves
#define KVSM  (2u * KHALF)                    // one KV buffer
#define ATT_SMEM ((QSM + 2u * KVSM) * 2u)     // 69632 B

__global__ void __launch_bounds__(128)
mqa_attn_h(const __half* __restrict__ qkv, __half* __restrict__ ao)
{
    extern __shared__ __half sh[];
    const uint32_t smb = smem_u32(sh);

    const int tid = threadIdx.x, wid = tid >> 5, lane = tid & 31;
    const int qt = gridDim.x - 1 - blockIdx.x;     // heavy tiles first
    const int h = blockIdx.y, b = blockIdx.z;
    const int q0 = qt * 128;
    const int ntk = 4 * qt + 4;                    // 32-wide kv tiles
    const int gid = lane >> 2, tig = lane & 3;
    const int m0w = wid * 32;

    // ---- Q tile load ----
    {
        const __half* qg = qkv + (size_t)(b * SB + q0) * NQKV + h * HD;
        #pragma unroll
        for (int i = 0; i < 16; i++) {
            const int c = i * 128 + tid;
            const int row = c >> 4, ch = c & 15;
            CP16(smb + (uint32_t)(row * 136 + ch * 8) * 2,
                 qg + (size_t)row * NQKV + ch * 8);
        }
    }
    CP_COMMIT();

    auto load_kv = [&](int jt, int buf) {
        const __half* g = qkv + (size_t)(b * SB + jt * KVT) * NQKV + NE;
        const uint32_t kb = QSM + (uint32_t)buf * KVSM;
        #pragma unroll
        for (int i = 0; i < 8; i++) {
            const int c = i * 128 + tid;           // 0..1023
            const int row = c >> 5, ch = c & 31;   // 32 rows x 32 chunks (K|V)
            const uint32_t off = kb + ((ch & 16) ? KHALF : 0u)
                               + (uint32_t)(row * 136 + (ch & 15) * 8);
            CP16(smb + off * 2, g + (size_t)row * NQKV + ch * 8);
        }
    };
    load_kv(0, 0);
    CP_COMMIT();

    // ones-column in V pad (cols 128..135), both buffers, written once
    if (tid < KVT) {
        uint4 onev = make_uint4(0x00003C00u, 0u, 0u, 0u);  // {1.0h, 0,...}
        *(uint4*)(sh + QSM + KHALF + (uint32_t)tid * 136u + 128u) = onev;
        *(uint4*)(sh + QSM + KVSM + KHALF + (uint32_t)tid * 136u + 128u) = onev;
    }
    CP_WAIT0();
    __syncthreads();

    float co[2][16][4];
    float cl[2][4];
    #pragma unroll
    for (int mt = 0; mt < 2; mt++) {
        #pragma unroll
        for (int n = 0; n < 16; n++)
            #pragma unroll
            for (int r = 0; r < 4; r++) co[mt][n][r] = 0.f;
        #pragma unroll
        for (int r = 0; r < 4; r++) cl[mt][r] = 0.f;
    }
    float mrow[2][2] = {{-1e30f, -1e30f}, {-1e30f, -1e30f}};

    const int a_r = lane & 15, a_c = (lane >> 4) * 8;
    const int k_row = ((lane >> 4) << 3) + (lane & 7);
    const int k_col = ((lane >> 3) & 1) * 8;
    const int v_row = ((lane >> 3) & 1) * 8 + (lane & 7);
    const int v_col = (lane >> 4) * 8;

    for (int jt = 0; jt < ntk; jt++) {
        if (jt > 0) { CP_WAIT0(); __syncthreads(); }
        if (jt + 1 < ntk) { load_kv(jt + 1, (jt + 1) & 1); CP_COMMIT(); }

        const int buf = jt & 1;
        const uint32_t kbB = smb + (QSM + (uint32_t)buf * KVSM) * 2u;
        const uint32_t vbB = kbB + KHALF * 2u;

        // ---- S = Q K^T (32 kv cols) ----
        float s[2][4][4];
        #pragma unroll
        for (int mt = 0; mt < 2; mt++)
            #pragma unroll
            for (int n = 0; n < 4; n++)
                #pragma unroll
                for (int r = 0; r < 4; r++) s[mt][n][r] = 0.f;

        #pragma unroll
        for (int kt = 0; kt < 8; kt++) {
            uint32_t a0[4], a1[4];
            LDSM_X4(a0[0], a0[1], a0[2], a0[3], smb +
                (uint32_t)((m0w + a_r) * 136 + kt * 16 + a_c) * 2);
            LDSM_X4(a1[0], a1[1], a1[2], a1[3], smb +
                (uint32_t)((m0w + 16 + a_r) * 136 + kt * 16 + a_c) * 2);
            #pragma unroll
            for (int np = 0; np < 2; np++) {
                uint32_t b0, b1, b2, b3;
                const uint32_t addr = kbB + (uint32_t)(
                    (np * 16 + k_row) * 136 + kt * 16 + k_col) * 2;
                LDSM_X4(b0, b1, b2, b3, addr);
                MMA16816(s[0][2*np][0], s[0][2*np][1], s[0][2*np][2], s[0][2*np][3],
                         a0[0], a0[1], a0[2], a0[3], b0, b1);
                MMA16816(s[0][2*np+1][0], s[0][2*np+1][1], s[0][2*np+1][2], s[0][2*np+1][3],
                         a0[0], a0[1], a0[2], a0[3], b2, b3);
                MMA16816(s[1][2*np][0], s[1][2*np][1], s[1][2*np][2], s[1][2*np][3],
                         a1[0], a1[1], a1[2], a1[3], b0, b1);
                MMA16816(s[1][2*np+1][0], s[1][2*np+1][1], s[1][2*np+1][2], s[1][2*np+1][3],
                         a1[0], a1[1], a1[2], a1[3], b2, b3);
            }
        }

        // ---- causal mask (last 4 tiles straddle the diagonal) ----
        if (jt >= ntk - 4) {
            #pragma unroll
            for (int mt = 0; mt < 2; mt++) {
                const int rg0 = q0 + m0w + mt * 16 + gid;
                const int rg1 = rg0 + 8;
                #pragma unroll
                for (int nt = 0; nt < 4; nt++) {
                    const int cg0 = jt * KVT + nt * 8 + tig * 2;
                    const int cg1 = cg0 + 1;
                    if (cg0 > rg0) s[mt][nt][0] = -1e30f;
                    if (cg1 > rg0) s[mt][nt][1] = -1e30f;
                    if (cg0 > rg1) s[mt][nt][2] = -1e30f;
                    if (cg1 > rg1) s[mt][nt][3] = -1e30f;
                }
            }
        }

        // ---- online softmax (log2-domain; P emerges packed fp16x2) ----
        uint32_t pa[2][2][4];
        #pragma unroll
        for (int mt = 0; mt < 2; mt++) {
            float mx0 = -1e30f, mx1 = -1e30f;
            #pragma unroll
            for (int nt = 0; nt < 4; nt++) {
                mx0 = fmaxf(mx0, fmaxf(s[mt][nt][0], s[mt][nt][1]));
                mx1 = fmaxf(mx1, fmaxf(s[mt][nt][2], s[mt][nt][3]));
            }
            mx0 = fmaxf(mx0, __shfl_xor_sync(0xffffffffu, mx0, 1));
            mx0 = fmaxf(mx0, __shfl_xor_sync(0xffffffffu, mx0, 2));
            mx1 = fmaxf(mx1, __shfl_xor_sync(0xffffffffu, mx1, 1));
            mx1 = fmaxf(mx1, __shfl_xor_sync(0xffffffffu, mx1, 2));

            const float mn0 = fmaxf(mrow[mt][0], mx0);
            const float mn1 = fmaxf(mrow[mt][1], mx1);
            const float al0 = ex2f(mrow[mt][0] - mn0);
            const float al1 = ex2f(mrow[mt][1] - mn1);
            mrow[mt][0] = mn0;
            mrow[mt][1] = mn1;

            #pragma unroll
            for (int nt = 0; nt < 4; nt++) {
                uint32_t p0 = pack_h2(s[mt][nt][0] - mn0, s[mt][nt][1] - mn0);
                uint32_t p1 = pack_h2(s[mt][nt][2] - mn1, s[mt][nt][3] - mn1);
                EX2H2(p0);
                EX2H2(p1);
                pa[mt][nt >> 1][(nt & 1) * 2]     = p0;
                pa[mt][nt >> 1][(nt & 1) * 2 + 1] = p1;
            }

            #pragma unroll
            for (int nt = 0; nt < 16; nt++) {
                co[mt][nt][0] *= al0; co[mt][nt][1] *= al0;
                co[mt][nt][2] *= al1; co[mt][nt][3] *= al1;
            }
            cl[mt][0] *= al0; cl[mt][1] *= al0;
            cl[mt][2] *= al1; cl[mt][3] *= al1;
        }

        // ---- O += P V ; l via ones-column MMA ----
        #pragma unroll
        for (int t = 0; t < 2; t++) {
            #pragma unroll
            for (int dp = 0; dp < 8; dp++) {
                uint32_t b0, b1, b2, b3;
                const uint32_t addr = vbB + (uint32_t)(
                    (t * 16 + v_row) * 136 + dp * 16 + v_col) * 2;
                LDSM_X4T(b0, b1, b2, b3, addr);
                #pragma unroll
                for (int mt = 0; mt < 2; mt++) {
                    MMA16816(co[mt][2*dp][0], co[mt][2*dp][1],
                             co[mt][2*dp][2], co[mt][2*dp][3],
                             pa[mt][t][0], pa[mt][t][1], pa[mt][t][2], pa[mt][t][3],
                             b0, b1);
                    MMA16816(co[mt][2*dp+1][0], co[mt][2*dp+1][1],
                             co[mt][2*dp+1][2], co[mt][2*dp+1][3],
                             pa[mt][t][0], pa[mt][t][1], pa[mt][t][2], pa[mt][t][3],
                             b2, b3);
                }
            }
            {
                uint32_t e0, e1;
                const uint32_t oaddr = vbB + (uint32_t)(
                    (t * 16 + v_row) * 136 + 128) * 2;
                LDSM_X2T(e0, e1, oaddr);
                #pragma unroll
                for (int mt = 0; mt < 2; mt++)
                    MMA16816(cl[mt][0], cl[mt][1], cl[mt][2], cl[mt][3],
                             pa[mt][t][0], pa[mt][t][1], pa[mt][t][2], pa[mt][t][3],
                             e0, e1);
            }
        }
    }

    // ---- finalize: l lives at tig==0 (V col 128); broadcast within quad ----
    #pragma unroll
    for (int mt = 0; mt < 2; mt++) {
        const float l0 = __shfl_sync(0xffffffffu, cl[mt][0], lane & 28);
        const float l1 = __shfl_sync(0xffffffffu, cl[mt][2], lane & 28);
        const float inv0 = 1.f / l0, inv1 = 1.f / l1;
        const int r0 = q0 + m0w + mt * 16 + gid, r1 = r0 + 8;
        __half* o0 = ao + (size_t)(b * SB + r0) * NE + h * HD;
        __half* o1 = ao + (size_t)(b * SB + r1) * NE + h * HD;
        #pragma unroll
        for (int nt = 0; nt < 16; nt++) {
            const int cc = nt * 8 + tig * 2;
            *(__half2*)(o0 + cc) = __floats2half2_rn(co[mt][nt][0] * inv0,
                                                     co[mt][nt][1] * inv0);
            *(__half2*)(o1 + cc) = __floats2half2_rn(co[mt][nt][2] * inv1,
                                                     co[mt][nt][3] * inv1);
        }
    }
}

// ---------------------------------------------------------------------------
extern "C" void kernel_launch(void* const* d_in, const int* in_sizes, int n_in,
                              void* d_out, int out_size)
{
    const float* x  = (const float*)d_in[0];
    const float* Wq = (const float*)d_in[1];
    const float* bq = (const float*)d_in[2];
    const float* Wk = (const float*)d_in[3];
    const float* bk = (const float*)d_in[4];
    const float* Wv = (const float*)d_in[5];
    const float* bv = (const float*)d_in[6];
    const float* Wo = (const float*)d_in[7];
    const float* bo = (const float*)d_in[8];
    float* out = (float*)d_out;

    __half *xh, *qkvh, *aoh, *wqkvh, *woh;
    float *bqkv;
    cudaGetSymbolAddress((void**)&xh,    g_xh);
    cudaGetSymbolAddress((void**)&qkvh,  g_qkvh);
    cudaGetSymbolAddress((void**)&aoh,   g_aoh);
    cudaGetSymbolAddress((void**)&wqkvh, g_wqkvh);
    cudaGetSymbolAddress((void**)&woh,   g_woh);
    cudaGetSymbolAddress((void**)&bqkv,  g_bqkv);

    cudaFuncSetAttribute(gemm_hmma64<__half>, cudaFuncAttributeMaxDynamicSharedMemorySize, GEMM_SMEM);
    cudaFuncSetAttribute(gemm_hmma64<float>,  cudaFuncAttributeMaxDynamicSharedMemorySize, GEMM_SMEM);
    cudaFuncSetAttribute(mqa_attn_h, cudaFuncAttributeMaxDynamicSharedMemorySize, ATT_SMEM);

    // 1/sqrt(128) * log2(e): logits in log2 domain
    const float scale = 0.08838834764831845f * 1.4426950408889634f;
    dim3 cblk(256);

    constexpr int WTOT = NQKV * NE + NE * NE;
    constexpr int GRID1 = (WTOT + NQKV * 4 + 1023) / 1024;
    conv_wb<<<GRID1, cblk>>>(Wq, Wk, Wv, Wo, bq, bk, bv, wqkvh, woh, bqkv, scale);
    conv_x<<<(MT * NE) / 1024, cblk>>>(x, xh, MT * NE);

    gemm_hmma64<__half><<<dim3(NQKV / 128, MT / 128), dim3(128), GEMM_SMEM>>>(
        xh, wqkvh, bqkv, qkvh, MT, NQKV, NE);
    // launch 4: attention (profiled slot)
    mqa_attn_h<<<dim3(SB / 128, NH, NB), dim3(128), ATT_SMEM>>>(qkvh, aoh);
    gemm_hmma64<float><<<dim3(NE / 128, MT / 128), dim3(128), GEMM_SMEM>>>(
        aoh, woh, bo, out, MT, NE, NE);
}

// round 13
// speedup vs baseline: 1.0051x; 1.0051x over previous
#include <cuda_runtime.h>
#include <cuda_fp16.h>
#include <cstdint>
#include <cstddef>

#define NE 2048
#define NH 16
#define HD 128
#define SB 2048
#define NB 2
#define MT 4096     // NB*SB
#define NQKV 2304   // 2048 (Q) + 128 (K) + 128 (V)

// ---------------- scratch (__device__ globals; no allocs) ------------------
__device__ __half g_xh   [MT * NE];
__device__ __half g_qkvh [MT * NQKV];      // fused Q|K|V, row stride 2304
__device__ __half g_aoh  [MT * NE];
__device__ __half g_wqkvh[NQKV * NE];
__device__ __half g_woh  [NE * NE];
__device__ float  g_bqkv [NQKV];

// ---------------- PTX helpers (sm_80-safe; no 'a' features) ----------------
#define CP16(sa, g)  asm volatile("cp.async.cg.shared.global [%0], [%1], 16;" :: "r"(sa), "l"(g))
#define CP_COMMIT()  asm volatile("cp.async.commit_group;" ::: "memory")
#define CP_WAIT1()   asm volatile("cp.async.wait_group 1;" ::: "memory")
#define CP_WAIT0()   asm volatile("cp.async.wait_group 0;" ::: "memory")

#define LDSM_X4(r0,r1,r2,r3, addr) \
    asm volatile("ldmatrix.sync.aligned.m8n8.x4.shared.b16 {%0,%1,%2,%3}, [%4];" \
        : "=r"(r0),"=r"(r1),"=r"(r2),"=r"(r3) : "r"(addr))
#define LDSM_X4T(r0,r1,r2,r3, addr) \
    asm volatile("ldmatrix.sync.aligned.m8n8.x4.trans.shared.b16 {%0,%1,%2,%3}, [%4];" \
        : "=r"(r0),"=r"(r1),"=r"(r2),"=r"(r3) : "r"(addr))
#define LDSM_X2T(r0,r1, addr) \
    asm volatile("ldmatrix.sync.aligned.m8n8.x2.trans.shared.b16 {%0,%1}, [%2];" \
        : "=r"(r0),"=r"(r1) : "r"(addr))
#define MMA16816(c0,c1,c2,c3, a0,a1,a2,a3, b0,b1) \
    asm volatile("mma.sync.aligned.m16n8k16.row.col.f32.f16.f16.f32 " \
        "{%0,%1,%2,%3}, {%4,%5,%6,%7}, {%8,%9}, {%0,%1,%2,%3};" \
        : "+f"(c0),"+f"(c1),"+f"(c2),"+f"(c3) \
        : "r"(a0),"r"(a1),"r"(a2),"r"(a3),"r"(b0),"r"(b1))
#define EX2H2(x) asm volatile("ex2.approx.f16x2 %0, %0;" : "+r"(x))

__device__ __forceinline__ uint32_t smem_u32(const void* p) {
    return (uint32_t)__cvta_generic_to_shared(p);
}
__device__ __forceinline__ uint32_t pack_h2(float a, float b) {
    __half2 h = __floats2half2_rn(a, b);
    return *(uint32_t*)&h;
}
__device__ __forceinline__ float ex2f(float x) {
    float y;
    asm("ex2.approx.ftz.f32 %0, %1;" : "=f"(y) : "f"(x));
    return y;
}

// ---------------- fused conversion kernels ----------------------------------
__global__ void __launch_bounds__(256)
conv_wb(const float* __restrict__ Wq, const float* __restrict__ Wk,
        const float* __restrict__ Wv, const float* __restrict__ Wo,
        const float* __restrict__ bq, const float* __restrict__ bk,
        const float* __restrict__ bv,
        __half* __restrict__ wqkvh, __half* __restrict__ woh,
        float* __restrict__ bqkv, float scale)
{
    constexpr int S0 = NE * NE;
    constexpr int S1 = S0 + HD * NE;
    constexpr int S2 = S1 + HD * NE;
    constexpr int S3 = S2 + NE * NE;
    const int i = (blockIdx.x * 256 + threadIdx.x) * 4;
    if (i < S0) {
        float4 v = *(const float4*)(Wq + i);
        __half2* o = (__half2*)(wqkvh + i);
        o[0] = __floats2half2_rn(v.x * scale, v.y * scale);
        o[1] = __floats2half2_rn(v.z * scale, v.w * scale);
    } else if (i < S1) {
        const int j = i - S0;
        float4 v = *(const float4*)(Wk + j);
        __half2* o = (__half2*)(wqkvh + NE * NE + j);
        o[0] = __floats2half2_rn(v.x, v.y);
        o[1] = __floats2half2_rn(v.z, v.w);
    } else if (i < S2) {
        const int j = i - S1;
        float4 v = *(const float4*)(Wv + j);
        __half2* o = (__half2*)(wqkvh + (NE + HD) * NE + j);
        o[0] = __floats2half2_rn(v.x, v.y);
        o[1] = __floats2half2_rn(v.z, v.w);
    } else if (i < S3) {
        const int j = i - S2;
        float4 v = *(const float4*)(Wo + j);
        __half2* o = (__half2*)(woh + j);
        o[0] = __floats2half2_rn(v.x, v.y);
        o[1] = __floats2half2_rn(v.z, v.w);
    } else {
        #pragma unroll
        for (int u = 0; u < 4; u++) {
            const int bidx = (i - S3) + u;
            if (bidx < NE)            bqkv[bidx] = bq[bidx] * scale;
            else if (bidx < NE + HD)  bqkv[bidx] = bk[bidx - NE];
            else if (bidx < NQKV)     bqkv[bidx] = bv[bidx - NE - HD];
        }
    }
}

__global__ void __launch_bounds__(256)
conv_x(const float* __restrict__ in, __half* __restrict__ out, int n)
{
    int i = (blockIdx.x * 256 + threadIdx.x) * 4;
    if (i < n) {
        float4 v = *(const float4*)(in + i);
        __half2* o = (__half2*)(out + i);
        o[0] = __floats2half2_rn(v.x, v.y);
        o[1] = __floats2half2_rn(v.z, v.w);
    }
}

// ---------------------------------------------------------------------------
// HMMA GEMM: 128x128 CTA tile, 4 warps, warp tile 64x64, BK=32,
// 3-stage cp.async, 2 CTAs/SM. (R7/R9-validated)
// ---------------------------------------------------------------------------
#define PAD 40
#define STG (128 * PAD)
#define AOFF(st) ((st) * STG * 2)
#define BOFF(st) (3 * STG * 2 + (st) * STG * 2)
#define GEMM_SMEM (6 * STG * 2)

template<typename OutT>
__global__ void __launch_bounds__(128, 2)
gemm_hmma64(const __half* __restrict__ A, const __half* __restrict__ B,
            const float* __restrict__ bias, OutT* __restrict__ C,
            int M, int N, int K)
{
    extern __shared__ __half sh[];
    const uint32_t smb = smem_u32(sh);

    const int tid  = threadIdx.x;
    const int wid  = tid >> 5;
    const int lane = tid & 31;
    const int bm = blockIdx.y * 128;
    const int bn = blockIdx.x * 128;
    const int m0 = (wid >> 1) * 64;
    const int n0 = (wid & 1) * 64;

    const int lrow = tid >> 2;
    const int lch  = tid & 3;

    float c[4][8][4];
    #pragma unroll
    for (int mt = 0; mt < 4; mt++)
        #pragma unroll
        for (int nt = 0; nt < 8; nt++)
            #pragma unroll
            for (int r = 0; r < 4; r++) c[mt][nt][r] = 0.f;

    const __half* Ab = A + (size_t)bm * K;
    const __half* Bb = B + (size_t)bn * K;
    const int nk = K / 32;

    auto load_stage = [&](int st, int k0) {
        #pragma unroll
        for (int r = 0; r < 4; r++) {
            const int row = lrow + r * 32;
            const uint32_t so = (uint32_t)(row * PAD + lch * 8) * 2;
            CP16(smb + AOFF(st) + so, Ab + (size_t)row * K + k0 + lch * 8);
            CP16(smb + BOFF(st) + so, Bb + (size_t)row * K + k0 + lch * 8);
        }
    };

    load_stage(0, 0);  CP_COMMIT();
    load_stage(1, 32); CP_COMMIT();

    const int a_r = lane & 15, a_c = (lane >> 4) * 8;
    const int b_row = ((lane >> 4) << 3) + (lane & 7);
    const int b_col = ((lane >> 3) & 1) * 8;

    for (int i = 0; i < nk; i++) {
        CP_WAIT1();
        __syncthreads();
        if (i + 2 < nk) load_stage((i + 2) % 3, (i + 2) * 32);
        CP_COMMIT();

        const int st = i % 3;
        #pragma unroll
        for (int ks = 0; ks < 2; ks++) {
            uint32_t a[4][4], b[8][2];
            #pragma unroll
            for (int mt = 0; mt < 4; mt++) {
                const uint32_t addr = smb + AOFF(st) +
                    (uint32_t)((m0 + mt * 16 + a_r) * PAD + ks * 16 + a_c) * 2;
                LDSM_X4(a[mt][0], a[mt][1], a[mt][2], a[mt][3], addr);
            }
            #pragma unroll
            for (int np = 0; np < 4; np++) {
                const uint32_t addr = smb + BOFF(st) +
                    (uint32_t)((n0 + np * 16 + b_row) * PAD + ks * 16 + b_col) * 2;
                LDSM_X4(b[2*np][0], b[2*np][1], b[2*np+1][0], b[2*np+1][1], addr);
            }
            #pragma unroll
            for (int mt = 0; mt < 4; mt++)
                #pragma unroll
                for (int nt = 0; nt < 8; nt++)
                    MMA16816(c[mt][nt][0], c[mt][nt][1], c[mt][nt][2], c[mt][nt][3],
                             a[mt][0], a[mt][1], a[mt][2], a[mt][3],
                             b[nt][0], b[nt][1]);
        }
        __syncthreads();
    }

    const int tr  = lane >> 2;
    const int tc2 = (lane & 3) * 2;
    #pragma unroll
    for (int mt = 0; mt < 4; mt++) {
        const int r0 = bm + m0 + mt * 16 + tr;
        #pragma unroll
        for (int nt = 0; nt < 8; nt++) {
            const int cc = bn + n0 + nt * 8 + tc2;
            const float bx = bias[cc], by = bias[cc + 1];
            if constexpr (sizeof(OutT) == 4) {
                *(float2*)&C[(size_t)r0 * N + cc] =
                    make_float2(c[mt][nt][0] + bx, c[mt][nt][1] + by);
                *(float2*)&C[(size_t)(r0 + 8) * N + cc] =
                    make_float2(c[mt][nt][2] + bx, c[mt][nt][3] + by);
            } else {
                *(__half2*)&C[(size_t)r0 * N + cc] =
                    __floats2half2_rn(c[mt][nt][0] + bx, c[mt][nt][1] + by);
                *(__half2*)&C[(size_t)(r0 + 8) * N + cc] =
                    __floats2half2_rn(c[mt][nt][2] + bx, c[mt][nt][3] + by);
            }
        }
    }
}

// ---------------------------------------------------------------------------
// HMMA MQA flash attention v5: 64 q-rows/CTA, 4 warps x 16 rows (one m-tile),
// 32-col KV tiles. Small footprint -> 3 CTAs/SM (12 warps) for latency
// coverage (R12 profile: nothing saturated, occ=11.3% was the limiter).
// SMEM halves: Q[64][136] @0; 2 x (K[32][136] + V[32][136]).
// ---------------------------------------------------------------------------
#define QROWS 64
#define QSM   8704u                           // Q halves (64 x 136)
#define KVT   32                              // kv tile rows
#define KHALF 4352u                           // one K (or V) tile halves
#define KVSM  (2u * KHALF)                    // one KV buffer
#define ATT_SMEM ((QSM + 2u * KVSM) * 2u)     // 52224 B; x3 = 156672 fits

__global__ void __launch_bounds__(128, 3)
mqa_attn_h(const __half* __restrict__ qkv, __half* __restrict__ ao)
{
    extern __shared__ __half sh[];
    const uint32_t smb = smem_u32(sh);

    const int tid = threadIdx.x, wid = tid >> 5, lane = tid & 31;
    const int qt = gridDim.x - 1 - blockIdx.x;     // heavy tiles first
    const int h = blockIdx.y, b = blockIdx.z;
    const int q0 = qt * QROWS;
    const int ntk = 2 * qt + 2;                    // 32-wide kv tiles
    const int gid = lane >> 2, tig = lane & 3;
    const int m0w = wid * 16;

    // ---- Q tile load: 64 rows x 128 cols ----
    {
        const __half* qg = qkv + (size_t)(b * SB + q0) * NQKV + h * HD;
        #pragma unroll
        for (int i = 0; i < 8; i++) {
            const int c = i * 128 + tid;
            const int row = c >> 4, ch = c & 15;
            CP16(smb + (uint32_t)(row * 136 + ch * 8) * 2,
                 qg + (size_t)row * NQKV + ch * 8);
        }
    }
    CP_COMMIT();

    auto load_kv = [&](int jt, int buf) {
        const __half* g = qkv + (size_t)(b * SB + jt * KVT) * NQKV + NE;
        const uint32_t kb = QSM + (uint32_t)buf * KVSM;
        #pragma unroll
        for (int i = 0; i < 8; i++) {
            const int c = i * 128 + tid;           // 0..1023
            const int row = c >> 5, ch = c & 31;   // 32 rows x (K|V)
            const uint32_t off = kb + ((ch & 16) ? KHALF : 0u)
                               + (uint32_t)(row * 136 + (ch & 15) * 8);
            CP16(smb + off * 2, g + (size_t)row * NQKV + ch * 8);
        }
    };
    load_kv(0, 0);
    CP_COMMIT();

    // ones-column in V pad (cols 128..135), both buffers, written once
    if (tid < KVT) {
        uint4 onev = make_uint4(0x00003C00u, 0u, 0u, 0u);  // {1.0h, 0,...}
        *(uint4*)(sh + QSM + KHALF + (uint32_t)tid * 136u + 128u) = onev;
        *(uint4*)(sh + QSM + KVSM + KHALF + (uint32_t)tid * 136u + 128u) = onev;
    }
    CP_WAIT0();
    __syncthreads();

    float co[16][4];
    float cl[4];
    #pragma unroll
    for (int n = 0; n < 16; n++)
        #pragma unroll
        for (int r = 0; r < 4; r++) co[n][r] = 0.f;
    #pragma unroll
    for (int r = 0; r < 4; r++) cl[r] = 0.f;
    float m0r = -1e30f, m1r = -1e30f;

    const int a_r = lane & 15, a_c = (lane >> 4) * 8;
    const int k_row = ((lane >> 4) << 3) + (lane & 7);
    const int k_col = ((lane >> 3) & 1) * 8;
    const int v_row = ((lane >> 3) & 1) * 8 + (lane & 7);
    const int v_col = (lane >> 4) * 8;

    for (int jt = 0; jt < ntk; jt++) {
        if (jt > 0) { CP_WAIT0(); __syncthreads(); }
        if (jt + 1 < ntk) { load_kv(jt + 1, (jt + 1) & 1); CP_COMMIT(); }

        const int buf = jt & 1;
        const uint32_t kbB = smb + (QSM + (uint32_t)buf * KVSM) * 2u;
        const uint32_t vbB = kbB + KHALF * 2u;

        // ---- S = Q K^T (16 rows x 32 kv cols) ----
        float s[4][4];
        #pragma unroll
        for (int n = 0; n < 4; n++)
            #pragma unroll
            for (int r = 0; r < 4; r++) s[n][r] = 0.f;

        #pragma unroll
        for (int kt = 0; kt < 8; kt++) {
            uint32_t a0[4];
            LDSM_X4(a0[0], a0[1], a0[2], a0[3], smb +
                (uint32_t)((m0w + a_r) * 136 + kt * 16 + a_c) * 2);
            #pragma unroll
            for (int np = 0; np < 2; np++) {
                uint32_t b0, b1, b2, b3;
                const uint32_t addr = kbB + (uint32_t)(
                    (np * 16 + k_row) * 136 + kt * 16 + k_col) * 2;
                LDSM_X4(b0, b1, b2, b3, addr);
                MMA16816(s[2*np][0], s[2*np][1], s[2*np][2], s[2*np][3],
                         a0[0], a0[1], a0[2], a0[3], b0, b1);
                MMA16816(s[2*np+1][0], s[2*np+1][1], s[2*np+1][2], s[2*np+1][3],
                         a0[0], a0[1], a0[2], a0[3], b2, b3);
            }
        }

        // ---- causal mask (last 2 tiles straddle the diagonal) ----
        if (jt >= ntk - 2) {
            const int rg0 = q0 + m0w + gid;
            const int rg1 = rg0 + 8;
            #pragma unroll
            for (int nt = 0; nt < 4; nt++) {
                const int cg0 = jt * KVT + nt * 8 + tig * 2;
                const int cg1 = cg0 + 1;
                if (cg0 > rg0) s[nt][0] = -1e30f;
                if (cg1 > rg0) s[nt][1] = -1e30f;
                if (cg0 > rg1) s[nt][2] = -1e30f;
                if (cg1 > rg1) s[nt][3] = -1e30f;
            }
        }

        // ---- online softmax (log2 domain, packed ex2) ----
        float mx0 = -1e30f, mx1 = -1e30f;
        #pragma unroll
        for (int nt = 0; nt < 4; nt++) {
            mx0 = fmaxf(mx0, fmaxf(s[nt][0], s[nt][1]));
            mx1 = fmaxf(mx1, fmaxf(s[nt][2], s[nt][3]));
        }
        mx0 = fmaxf(mx0, __shfl_xor_sync(0xffffffffu, mx0, 1));
        mx0 = fmaxf(mx0, __shfl_xor_sync(0xffffffffu, mx0, 2));
        mx1 = fmaxf(mx1, __shfl_xor_sync(0xffffffffu, mx1, 1));
        mx1 = fmaxf(mx1, __shfl_xor_sync(0xffffffffu, mx1, 2));

        const float mn0 = fmaxf(m0r, mx0);
        const float mn1 = fmaxf(m1r, mx1);
        const float al0 = ex2f(m0r - mn0);
        const float al1 = ex2f(m1r - mn1);
        m0r = mn0;
        m1r = mn1;

        uint32_t pa[2][4];
        #pragma unroll
        for (int nt = 0; nt < 4; nt++) {
            uint32_t p0 = pack_h2(s[nt][0] - mn0, s[nt][1] - mn0);
            uint32_t p1 = pack_h2(s[nt][2] - mn1, s[nt][3] - mn1);
            EX2H2(p0);
            EX2H2(p1);
            pa[nt >> 1][(nt & 1) * 2]     = p0;
            pa[nt >> 1][(nt & 1) * 2 + 1] = p1;
        }

        #pragma unroll
        for (int nt = 0; nt < 16; nt++) {
            co[nt][0] *= al0; co[nt][1] *= al0;
            co[nt][2] *= al1; co[nt][3] *= al1;
        }
        cl[0] *= al0; cl[1] *= al0;
        cl[2] *= al1; cl[3] *= al1;

        // ---- O += P V ; l via ones-column MMA ----
        #pragma unroll
        for (int t = 0; t < 2; t++) {
            #pragma unroll
            for (int dp = 0; dp < 8; dp++) {
                uint32_t b0, b1, b2, b3;
                const uint32_t addr = vbB + (uint32_t)(
                    (t * 16 + v_row) * 136 + dp * 16 + v_col) * 2;
                LDSM_X4T(b0, b1, b2, b3, addr);
                MMA16816(co[2*dp][0], co[2*dp][1], co[2*dp][2], co[2*dp][3],
                         pa[t][0], pa[t][1], pa[t][2], pa[t][3], b0, b1);
                MMA16816(co[2*dp+1][0], co[2*dp+1][1], co[2*dp+1][2], co[2*dp+1][3],
                         pa[t][0], pa[t][1], pa[t][2], pa[t][3], b2, b3);
            }
            {
                uint32_t e0, e1;
                const uint32_t oaddr = vbB + (uint32_t)(
                    (t * 16 + v_row) * 136 + 128) * 2;
                LDSM_X2T(e0, e1, oaddr);
                MMA16816(cl[0], cl[1], cl[2], cl[3],
                         pa[t][0], pa[t][1], pa[t][2], pa[t][3], e0, e1);
            }
        }
    }

    // ---- finalize ----
    const float l0 = __shfl_sync(0xffffffffu, cl[0], lane & 28);
    const float l1 = __shfl_sync(0xffffffffu, cl[2], lane & 28);
    const float inv0 = 1.f / l0, inv1 = 1.f / l1;
    const int r0 = q0 + m0w + gid, r1 = r0 + 8;
    __half* o0 = ao + (size_t)(b * SB + r0) * NE + h * HD;
    __half* o1 = ao + (size_t)(b * SB + r1) * NE + h * HD;
    #pragma unroll
    for (int nt = 0; nt < 16; nt++) {
        const int cc = nt * 8 + tig * 2;
        *(__half2*)(o0 + cc) = __floats2half2_rn(co[nt][0] * inv0,
                                                 co[nt][1] * inv0);
        *(__half2*)(o1 + cc) = __floats2half2_rn(co[nt][2] * inv1,
                                                 co[nt][3] * inv1);
    }
}

// ---------------------------------------------------------------------------
extern "C" void kernel_launch(void* const* d_in, const int* in_sizes, int n_in,
                              void* d_out, int out_size)
{
    const float* x  = (const float*)d_in[0];
    const float* Wq = (const float*)d_in[1];
    const float* bq = (const float*)d_in[2];
    const float* Wk = (const float*)d_in[3];
    const float* bk = (const float*)d_in[4];
    const float* Wv = (const float*)d_in[5];
    const float* bv = (const float*)d_in[6];
    const float* Wo = (const float*)d_in[7];
    const float* bo = (const float*)d_in[8];
    float* out = (float*)d_out;

    __half *xh, *qkvh, *aoh, *wqkvh, *woh;
    float *bqkv;
    cudaGetSymbolAddress((void**)&xh,    g_xh);
    cudaGetSymbolAddress((void**)&qkvh,  g_qkvh);
    cudaGetSymbolAddress((void**)&aoh,   g_aoh);
    cudaGetSymbolAddress((void**)&wqkvh, g_wqkvh);
    cudaGetSymbolAddress((void**)&woh,   g_woh);
    cudaGetSymbolAddress((void**)&bqkv,  g_bqkv);

    cudaFuncSetAttribute(gemm_hmma64<__half>, cudaFuncAttributeMaxDynamicSharedMemorySize, GEMM_SMEM);
    cudaFuncSetAttribute(gemm_hmma64<float>,  cudaFuncAttributeMaxDynamicSharedMemorySize, GEMM_SMEM);
    cudaFuncSetAttribute(mqa_attn_h, cudaFuncAttributeMaxDynamicSharedMemorySize, ATT_SMEM);

    // 1/sqrt(128) * log2(e): logits in log2 domain
    const float scale = 0.08838834764831845f * 1.4426950408889634f;
    dim3 cblk(256);

    constexpr int WTOT = NQKV * NE + NE * NE;
    constexpr int GRID1 = (WTOT + NQKV * 4 + 1023) / 1024;
    conv_wb<<<GRID1, cblk>>>(Wq, Wk, Wv, Wo, bq, bk, bv, wqkvh, woh, bqkv, scale);
    conv_x<<<(MT * NE) / 1024, cblk>>>(x, xh, MT * NE);

    gemm_hmma64<__half><<<dim3(NQKV / 128, MT / 128), dim3(128), GEMM_SMEM>>>(
        xh, wqkvh, bqkv, qkvh, MT, NQKV, NE);
    // launch 4: attention (profiled slot) — 64 q-rows per CTA, 3 CTAs/SM
    mqa_attn_h<<<dim3(SB / QROWS, NH, NB), dim3(128), ATT_SMEM>>>(qkvh, aoh);
    gemm_hmma64<float><<<dim3(NE / 128, MT / 128), dim3(128), GEMM_SMEM>>>(
        aoh, woh, bo, out, MT, NE, NE);
}

// round 14
// speedup vs baseline: 1.0069x; 1.0018x over previous
#include <cuda_runtime.h>
#include <cuda_fp16.h>
#include <cstdint>
#include <cstddef>

#define NE 2048
#define NH 16
#define HD 128
#define SB 2048
#define NB 2
#define MT 4096     // NB*SB
#define NQKV 2304   // 2048 (Q) + 128 (K) + 128 (V)

// ---------------- scratch (__device__ globals; no allocs) ------------------
__device__ __half g_xh   [MT * NE];
__device__ __half g_qkvh [MT * NQKV];      // fused Q|K|V, row stride 2304
__device__ __half g_aoh  [MT * NE];
__device__ __half g_wqkvh[NQKV * NE];
__device__ __half g_woh  [NE * NE];
__device__ float  g_bqkv [NQKV];

// ---------------- PTX helpers (sm_80-safe; no 'a' features) ----------------
#define CP16(sa, g)  asm volatile("cp.async.cg.shared.global [%0], [%1], 16;" :: "r"(sa), "l"(g))
#define CP_COMMIT()  asm volatile("cp.async.commit_group;" ::: "memory")
#define CP_WAIT1()   asm volatile("cp.async.wait_group 1;" ::: "memory")
#define CP_WAIT0()   asm volatile("cp.async.wait_group 0;" ::: "memory")

#define LDSM_X4(r0,r1,r2,r3, addr) \
    asm volatile("ldmatrix.sync.aligned.m8n8.x4.shared.b16 {%0,%1,%2,%3}, [%4];" \
        : "=r"(r0),"=r"(r1),"=r"(r2),"=r"(r3) : "r"(addr))
#define LDSM_X4T(r0,r1,r2,r3, addr) \
    asm volatile("ldmatrix.sync.aligned.m8n8.x4.trans.shared.b16 {%0,%1,%2,%3}, [%4];" \
        : "=r"(r0),"=r"(r1),"=r"(r2),"=r"(r3) : "r"(addr))
#define LDSM_X2T(r0,r1, addr) \
    asm volatile("ldmatrix.sync.aligned.m8n8.x2.trans.shared.b16 {%0,%1}, [%2];" \
        : "=r"(r0),"=r"(r1) : "r"(addr))
#define MMA16816(c0,c1,c2,c3, a0,a1,a2,a3, b0,b1) \
    asm volatile("mma.sync.aligned.m16n8k16.row.col.f32.f16.f16.f32 " \
        "{%0,%1,%2,%3}, {%4,%5,%6,%7}, {%8,%9}, {%0,%1,%2,%3};" \
        : "+f"(c0),"+f"(c1),"+f"(c2),"+f"(c3) \
        : "r"(a0),"r"(a1),"r"(a2),"r"(a3),"r"(b0),"r"(b1))
#define EX2H2(x) asm volatile("ex2.approx.f16x2 %0, %0;" : "+r"(x))

__device__ __forceinline__ uint32_t smem_u32(const void* p) {
    return (uint32_t)__cvta_generic_to_shared(p);
}
__device__ __forceinline__ uint32_t pack_h2(float a, float b) {
    __half2 h = __floats2half2_rn(a, b);
    return *(uint32_t*)&h;
}
__device__ __forceinline__ float ex2f(float x) {
    float y;
    asm("ex2.approx.ftz.f32 %0, %1;" : "=f"(y) : "f"(x));
    return y;
}

// ---------------- fused conversion kernels ----------------------------------
__global__ void __launch_bounds__(256)
conv_wb(const float* __restrict__ Wq, const float* __restrict__ Wk,
        const float* __restrict__ Wv, const float* __restrict__ Wo,
        const float* __restrict__ bq, const float* __restrict__ bk,
        const float* __restrict__ bv,
        __half* __restrict__ wqkvh, __half* __restrict__ woh,
        float* __restrict__ bqkv, float scale)
{
    constexpr int S0 = NE * NE;
    constexpr int S1 = S0 + HD * NE;
    constexpr int S2 = S1 + HD * NE;
    constexpr int S3 = S2 + NE * NE;
    const int i = (blockIdx.x * 256 + threadIdx.x) * 4;
    if (i < S0) {
        float4 v = *(const float4*)(Wq + i);
        __half2* o = (__half2*)(wqkvh + i);
        o[0] = __floats2half2_rn(v.x * scale, v.y * scale);
        o[1] = __floats2half2_rn(v.z * scale, v.w * scale);
    } else if (i < S1) {
        const int j = i - S0;
        float4 v = *(const float4*)(Wk + j);
        __half2* o = (__half2*)(wqkvh + NE * NE + j);
        o[0] = __floats2half2_rn(v.x, v.y);
        o[1] = __floats2half2_rn(v.z, v.w);
    } else if (i < S2) {
        const int j = i - S1;
        float4 v = *(const float4*)(Wv + j);
        __half2* o = (__half2*)(wqkvh + (NE + HD) * NE + j);
        o[0] = __floats2half2_rn(v.x, v.y);
        o[1] = __floats2half2_rn(v.z, v.w);
    } else if (i < S3) {
        const int j = i - S2;
        float4 v = *(const float4*)(Wo + j);
        __half2* o = (__half2*)(woh + j);
        o[0] = __floats2half2_rn(v.x, v.y);
        o[1] = __floats2half2_rn(v.z, v.w);
    } else {
        #pragma unroll
        for (int u = 0; u < 4; u++) {
            const int bidx = (i - S3) + u;
            if (bidx < NE)            bqkv[bidx] = bq[bidx] * scale;
            else if (bidx < NE + HD)  bqkv[bidx] = bk[bidx - NE];
            else if (bidx < NQKV)     bqkv[bidx] = bv[bidx - NE - HD];
        }
    }
}

__global__ void __launch_bounds__(256)
conv_x(const float* __restrict__ in, __half* __restrict__ out, int n)
{
    int i = (blockIdx.x * 256 + threadIdx.x) * 4;
    if (i < n) {
        float4 v = *(const float4*)(in + i);
        __half2* o = (__half2*)(out + i);
        o[0] = __floats2half2_rn(v.x, v.y);
        o[1] = __floats2half2_rn(v.z, v.w);
    }
}

// ---------------------------------------------------------------------------
// HMMA GEMM: 128x128 CTA tile, 4 warps, warp tile 64x64, BK=32,
// 3-stage cp.async, 2 CTAs/SM. (R7/R9-validated)
// ---------------------------------------------------------------------------
#define PAD 40
#define STG (128 * PAD)
#define AOFF(st) ((st) * STG * 2)
#define BOFF(st) (3 * STG * 2 + (st) * STG * 2)
#define GEMM_SMEM (6 * STG * 2)

template<typename OutT>
__global__ void __launch_bounds__(128, 2)
gemm_hmma64(const __half* __restrict__ A, const __half* __restrict__ B,
            const float* __restrict__ bias, OutT* __restrict__ C,
            int M, int N, int K)
{
    extern __shared__ __half sh[];
    const uint32_t smb = smem_u32(sh);

    const int tid  = threadIdx.x;
    const int wid  = tid >> 5;
    const int lane = tid & 31;
    const int bm = blockIdx.y * 128;
    const int bn = blockIdx.x * 128;
    const int m0 = (wid >> 1) * 64;
    const int n0 = (wid & 1) * 64;

    const int lrow = tid >> 2;
    const int lch  = tid & 3;

    float c[4][8][4];
    #pragma unroll
    for (int mt = 0; mt < 4; mt++)
        #pragma unroll
        for (int nt = 0; nt < 8; nt++)
            #pragma unroll
            for (int r = 0; r < 4; r++) c[mt][nt][r] = 0.f;

    const __half* Ab = A + (size_t)bm * K;
    const __half* Bb = B + (size_t)bn * K;
    const int nk = K / 32;

    auto load_stage = [&](int st, int k0) {
        #pragma unroll
        for (int r = 0; r < 4; r++) {
            const int row = lrow + r * 32;
            const uint32_t so = (uint32_t)(row * PAD + lch * 8) * 2;
            CP16(smb + AOFF(st) + so, Ab + (size_t)row * K + k0 + lch * 8);
            CP16(smb + BOFF(st) + so, Bb + (size_t)row * K + k0 + lch * 8);
        }
    };

    load_stage(0, 0);  CP_COMMIT();
    load_stage(1, 32); CP_COMMIT();

    const int a_r = lane & 15, a_c = (lane >> 4) * 8;
    const int b_row = ((lane >> 4) << 3) + (lane & 7);
    const int b_col = ((lane >> 3) & 1) * 8;

    for (int i = 0; i < nk; i++) {
        CP_WAIT1();
        __syncthreads();
        if (i + 2 < nk) load_stage((i + 2) % 3, (i + 2) * 32);
        CP_COMMIT();

        const int st = i % 3;
        #pragma unroll
        for (int ks = 0; ks < 2; ks++) {
            uint32_t a[4][4], b[8][2];
            #pragma unroll
            for (int mt = 0; mt < 4; mt++) {
                const uint32_t addr = smb + AOFF(st) +
                    (uint32_t)((m0 + mt * 16 + a_r) * PAD + ks * 16 + a_c) * 2;
                LDSM_X4(a[mt][0], a[mt][1], a[mt][2], a[mt][3], addr);
            }
            #pragma unroll
            for (int np = 0; np < 4; np++) {
                const uint32_t addr = smb + BOFF(st) +
                    (uint32_t)((n0 + np * 16 + b_row) * PAD + ks * 16 + b_col) * 2;
                LDSM_X4(b[2*np][0], b[2*np][1], b[2*np+1][0], b[2*np+1][1], addr);
            }
            #pragma unroll
            for (int mt = 0; mt < 4; mt++)
                #pragma unroll
                for (int nt = 0; nt < 8; nt++)
                    MMA16816(c[mt][nt][0], c[mt][nt][1], c[mt][nt][2], c[mt][nt][3],
                             a[mt][0], a[mt][1], a[mt][2], a[mt][3],
                             b[nt][0], b[nt][1]);
        }
        __syncthreads();
    }

    const int tr  = lane >> 2;
    const int tc2 = (lane & 3) * 2;
    #pragma unroll
    for (int mt = 0; mt < 4; mt++) {
        const int r0 = bm + m0 + mt * 16 + tr;
        #pragma unroll
        for (int nt = 0; nt < 8; nt++) {
            const int cc = bn + n0 + nt * 8 + tc2;
            const float bx = bias[cc], by = bias[cc + 1];
            if constexpr (sizeof(OutT) == 4) {
                *(float2*)&C[(size_t)r0 * N + cc] =
                    make_float2(c[mt][nt][0] + bx, c[mt][nt][1] + by);
                *(float2*)&C[(size_t)(r0 + 8) * N + cc] =
                    make_float2(c[mt][nt][2] + bx, c[mt][nt][3] + by);
            } else {
                *(__half2*)&C[(size_t)r0 * N + cc] =
                    __floats2half2_rn(c[mt][nt][0] + bx, c[mt][nt][1] + by);
                *(__half2*)&C[(size_t)(r0 + 8) * N + cc] =
                    __floats2half2_rn(c[mt][nt][2] + bx, c[mt][nt][3] + by);
            }
        }
    }
}

// ---------------------------------------------------------------------------
// HMMA MQA flash attention v6: 64 q-rows/CTA, 4 warps x 16 rows, 32-col KV
// tiles, SOFTWARE-PIPELINED: ntk is even -> unroll by 2 with ping-pong S regs
// and 3 KV buffers; the S-MMA block of tile j+1 issues inside tile j's
// softmax latency shadow (R11-R13 showed the serial chain, not port/regs/
// occupancy, limits this kernel).
// ---------------------------------------------------------------------------
#define QROWS 64
#define QSM   8704u                           // Q halves (64 x 136)
#define KVT   32                              // kv tile rows
#define KHALF 4352u                           // one K (or V) tile halves
#define KVSM  (2u * KHALF)                    // one KV buffer (K+V)
#define ATT_SMEM ((QSM + 3u * KVSM) * 2u)     // 69632 B

__global__ void __launch_bounds__(128)
mqa_attn_h(const __half* __restrict__ qkv, __half* __restrict__ ao)
{
    extern __shared__ __half sh[];
    const uint32_t smb = smem_u32(sh);

    const int tid = threadIdx.x, wid = tid >> 5, lane = tid & 31;
    const int qt = gridDim.x - 1 - blockIdx.x;     // heavy tiles first
    const int h = blockIdx.y, b = blockIdx.z;
    const int q0 = qt * QROWS;
    const int ntk = 2 * qt + 2;                    // always even
    const int gid = lane >> 2, tig = lane & 3;
    const int m0w = wid * 16;

    // ---- Q tile load ----
    {
        const __half* qg = qkv + (size_t)(b * SB + q0) * NQKV + h * HD;
        #pragma unroll
        for (int i = 0; i < 8; i++) {
            const int c = i * 128 + tid;
            const int row = c >> 4, ch = c & 15;
            CP16(smb + (uint32_t)(row * 136 + ch * 8) * 2,
                 qg + (size_t)row * NQKV + ch * 8);
        }
    }
    CP_COMMIT();

    auto load_kv = [&](int jt, int buf) {
        const __half* g = qkv + (size_t)(b * SB + jt * KVT) * NQKV + NE;
        const uint32_t kb = QSM + (uint32_t)buf * KVSM;
        #pragma unroll
        for (int i = 0; i < 8; i++) {
            const int c = i * 128 + tid;
            const int row = c >> 5, ch = c & 31;
            const uint32_t off = kb + ((ch & 16) ? KHALF : 0u)
                               + (uint32_t)(row * 136 + (ch & 15) * 8);
            CP16(smb + off * 2, g + (size_t)row * NQKV + ch * 8);
        }
    };
    load_kv(0, 0);
    CP_COMMIT();

    // ones-columns in V pad (cols 128..135) for all 3 buffers, written once
    if (tid < KVT) {
        uint4 onev = make_uint4(0x00003C00u, 0u, 0u, 0u);
        #pragma unroll
        for (int bfi = 0; bfi < 3; bfi++)
            *(uint4*)(sh + QSM + (uint32_t)bfi * KVSM + KHALF
                      + (uint32_t)tid * 136u + 128u) = onev;
    }
    CP_WAIT0();
    __syncthreads();

    // prefetch kv(1) (ntk >= 2 always)
    load_kv(1, 1);
    CP_COMMIT();

    float co[16][4];
    float cl[4];
    #pragma unroll
    for (int n = 0; n < 16; n++)
        #pragma unroll
        for (int r = 0; r < 4; r++) co[n][r] = 0.f;
    #pragma unroll
    for (int r = 0; r < 4; r++) cl[r] = 0.f;
    float m0r = -1e30f, m1r = -1e30f;

    const int a_r = lane & 15, a_c = (lane >> 4) * 8;
    const int k_row = ((lane >> 4) << 3) + (lane & 7);
    const int k_col = ((lane >> 3) & 1) * 8;
    const int v_row = ((lane >> 3) & 1) * 8 + (lane & 7);
    const int v_col = (lane >> 4) * 8;

    float s_a[4][4], s_b[4][4];
    uint32_t pa[2][4];

    // ---- helpers ----
    auto computeS = [&](float (&s)[4][4], int buf) {
        const uint32_t kbB = smb + (QSM + (uint32_t)buf * KVSM) * 2u;
        #pragma unroll
        for (int n = 0; n < 4; n++)
            #pragma unroll
            for (int r = 0; r < 4; r++) s[n][r] = 0.f;
        #pragma unroll
        for (int kt = 0; kt < 8; kt++) {
            uint32_t a0[4];
            LDSM_X4(a0[0], a0[1], a0[2], a0[3], smb +
                (uint32_t)((m0w + a_r) * 136 + kt * 16 + a_c) * 2);
            #pragma unroll
            for (int np = 0; np < 2; np++) {
                uint32_t b0, b1, b2, b3;
                const uint32_t addr = kbB + (uint32_t)(
                    (np * 16 + k_row) * 136 + kt * 16 + k_col) * 2;
                LDSM_X4(b0, b1, b2, b3, addr);
                MMA16816(s[2*np][0], s[2*np][1], s[2*np][2], s[2*np][3],
                         a0[0], a0[1], a0[2], a0[3], b0, b1);
                MMA16816(s[2*np+1][0], s[2*np+1][1], s[2*np+1][2], s[2*np+1][3],
                         a0[0], a0[1], a0[2], a0[3], b2, b3);
            }
        }
    };
    auto applyMask = [&](float (&s)[4][4], int jtile) {
        const int rg0 = q0 + m0w + gid;
        const int rg1 = rg0 + 8;
        #pragma unroll
        for (int nt = 0; nt < 4; nt++) {
            const int cg0 = jtile * KVT + nt * 8 + tig * 2;
            const int cg1 = cg0 + 1;
            if (cg0 > rg0) s[nt][0] = -1e30f;
            if (cg1 > rg0) s[nt][1] = -1e30f;
            if (cg0 > rg1) s[nt][2] = -1e30f;
            if (cg1 > rg1) s[nt][3] = -1e30f;
        }
    };
    auto sfinish = [&](float (&s)[4][4], float mx0, float mx1) {
        const float mn0 = fmaxf(m0r, mx0);
        const float mn1 = fmaxf(m1r, mx1);
        const float al0 = ex2f(m0r - mn0);
        const float al1 = ex2f(m1r - mn1);
        m0r = mn0;
        m1r = mn1;
        #pragma unroll
        for (int nt = 0; nt < 4; nt++) {
            uint32_t p0 = pack_h2(s[nt][0] - mn0, s[nt][1] - mn0);
            uint32_t p1 = pack_h2(s[nt][2] - mn1, s[nt][3] - mn1);
            EX2H2(p0);
            EX2H2(p1);
            pa[nt >> 1][(nt & 1) * 2]     = p0;
            pa[nt >> 1][(nt & 1) * 2 + 1] = p1;
        }
        #pragma unroll
        for (int nt = 0; nt < 16; nt++) {
            co[nt][0] *= al0; co[nt][1] *= al0;
            co[nt][2] *= al1; co[nt][3] *= al1;
        }
        cl[0] *= al0; cl[1] *= al0;
        cl[2] *= al1; cl[3] *= al1;
    };
    auto pv = [&](int buf) {
        const uint32_t vbB = smb + (QSM + (uint32_t)buf * KVSM + KHALF) * 2u;
        #pragma unroll
        for (int t = 0; t < 2; t++) {
            #pragma unroll
            for (int dp = 0; dp < 8; dp++) {
                uint32_t b0, b1, b2, b3;
                const uint32_t addr = vbB + (uint32_t)(
                    (t * 16 + v_row) * 136 + dp * 16 + v_col) * 2;
                LDSM_X4T(b0, b1, b2, b3, addr);
                MMA16816(co[2*dp][0], co[2*dp][1], co[2*dp][2], co[2*dp][3],
                         pa[t][0], pa[t][1], pa[t][2], pa[t][3], b0, b1);
                MMA16816(co[2*dp+1][0], co[2*dp+1][1], co[2*dp+1][2], co[2*dp+1][3],
                         pa[t][0], pa[t][1], pa[t][2], pa[t][3], b2, b3);
            }
            uint32_t e0, e1;
            const uint32_t oaddr = vbB + (uint32_t)(
                (t * 16 + v_row) * 136 + 128) * 2;
            LDSM_X2T(e0, e1, oaddr);
            MMA16816(cl[0], cl[1], cl[2], cl[3],
                     pa[t][0], pa[t][1], pa[t][2], pa[t][3], e0, e1);
        }
    };
    auto rowmax = [&](float (&s)[4][4], float& mx0, float& mx1) {
        mx0 = -1e30f; mx1 = -1e30f;
        #pragma unroll
        for (int nt = 0; nt < 4; nt++) {
            mx0 = fmaxf(mx0, fmaxf(s[nt][0], s[nt][1]));
            mx1 = fmaxf(mx1, fmaxf(s[nt][2], s[nt][3]));
        }
        mx0 = fmaxf(mx0, __shfl_xor_sync(0xffffffffu, mx0, 1));
        mx0 = fmaxf(mx0, __shfl_xor_sync(0xffffffffu, mx0, 2));
        mx1 = fmaxf(mx1, __shfl_xor_sync(0xffffffffu, mx1, 1));
        mx1 = fmaxf(mx1, __shfl_xor_sync(0xffffffffu, mx1, 2));
    };

    // ---- prologue: S(0) ----
    computeS(s_a, 0);

    int ib0 = 0, ib1 = 1, ib2 = 2;   // bufs of tiles jt, jt+1, jt+2
    for (int jt = 0; jt < ntk; jt += 2) {
        const bool last = (jt + 2 >= ntk);

        // ===== step A: tile jt (s_a); overlap S(jt+1) with softmax =====
        CP_WAIT0();
        __syncthreads();
        if (!last) load_kv(jt + 2, ib2);
        CP_COMMIT();
        if (last) applyMask(s_a, jt);
        float mx0, mx1;
        rowmax(s_a, mx0, mx1);
        computeS(s_b, ib1);              // independent: fills shfl/ex2 shadow
        sfinish(s_a, mx0, mx1);
        pv(ib0);

        // ===== step B: tile jt+1 (s_b); overlap S(jt+2) =====
        CP_WAIT0();
        __syncthreads();
        if (jt + 3 < ntk) load_kv(jt + 3, ib0);
        CP_COMMIT();
        if (last) applyMask(s_b, jt + 1);
        rowmax(s_b, mx0, mx1);
        if (!last) computeS(s_a, ib2);
        sfinish(s_b, mx0, mx1);
        pv(ib1);

        // rotate buffers: (jt+2, jt+3, jt+4) % 3
        const int t = ib1;
        ib1 = ib0;
        ib0 = ib2;
        ib2 = t;
    }

    // ---- finalize ----
    const float l0 = __shfl_sync(0xffffffffu, cl[0], lane & 28);
    const float l1 = __shfl_sync(0xffffffffu, cl[2], lane & 28);
    const float inv0 = 1.f / l0, inv1 = 1.f / l1;
    const int r0 = q0 + m0w + gid, r1 = r0 + 8;
    __half* o0 = ao + (size_t)(b * SB + r0) * NE + h * HD;
    __half* o1 = ao + (size_t)(b * SB + r1) * NE + h * HD;
    #pragma unroll
    for (int nt = 0; nt < 16; nt++) {
        const int cc = nt * 8 + tig * 2;
        *(__half2*)(o0 + cc) = __floats2half2_rn(co[nt][0] * inv0,
                                                 co[nt][1] * inv0);
        *(__half2*)(o1 + cc) = __floats2half2_rn(co[nt][2] * inv1,
                                                 co[nt][3] * inv1);
    }
}

// ---------------------------------------------------------------------------
extern "C" void kernel_launch(void* const* d_in, const int* in_sizes, int n_in,
                              void* d_out, int out_size)
{
    const float* x  = (const float*)d_in[0];
    const float* Wq = (const float*)d_in[1];
    const float* bq = (const float*)d_in[2];
    const float* Wk = (const float*)d_in[3];
    const float* bk = (const float*)d_in[4];
    const float* Wv = (const float*)d_in[5];
    const float* bv = (const float*)d_in[6];
    const float* Wo = (const float*)d_in[7];
    const float* bo = (const float*)d_in[8];
    float* out = (float*)d_out;

    __half *xh, *qkvh, *aoh, *wqkvh, *woh;
    float *bqkv;
    cudaGetSymbolAddress((void**)&xh,    g_xh);
    cudaGetSymbolAddress((void**)&qkvh,  g_qkvh);
    cudaGetSymbolAddress((void**)&aoh,   g_aoh);
    cudaGetSymbolAddress((void**)&wqkvh, g_wqkvh);
    cudaGetSymbolAddress((void**)&woh,   g_woh);
    cudaGetSymbolAddress((void**)&bqkv,  g_bqkv);

    cudaFuncSetAttribute(gemm_hmma64<__half>, cudaFuncAttributeMaxDynamicSharedMemorySize, GEMM_SMEM);
    cudaFuncSetAttribute(gemm_hmma64<float>,  cudaFuncAttributeMaxDynamicSharedMemorySize, GEMM_SMEM);
    cudaFuncSetAttribute(mqa_attn_h, cudaFuncAttributeMaxDynamicSharedMemorySize, ATT_SMEM);

    // 1/sqrt(128) * log2(e): logits in log2 domain
    const float scale = 0.08838834764831845f * 1.4426950408889634f;
    dim3 cblk(256);

    constexpr int WTOT = NQKV * NE + NE * NE;
    constexpr int GRID1 = (WTOT + NQKV * 4 + 1023) / 1024;
    conv_wb<<<GRID1, cblk>>>(Wq, Wk, Wv, Wo, bq, bk, bv, wqkvh, woh, bqkv, scale);
    conv_x<<<(MT * NE) / 1024, cblk>>>(x, xh, MT * NE);

    gemm_hmma64<__half><<<dim3(NQKV / 128, MT / 128), dim3(128), GEMM_SMEM>>>(
        xh, wqkvh, bqkv, qkvh, MT, NQKV, NE);
    // launch 4: attention (profiled slot)
    mqa_attn_h<<<dim3(SB / QROWS, NH, NB), dim3(128), ATT_SMEM>>>(qkvh, aoh);
    gemm_hmma64<float><<<dim3(NE / 128, MT / 128), dim3(128), GEMM_SMEM>>>(
        aoh, woh, bo, out, MT, NE, NE);
}

// round 15
// speedup vs baseline: 1.0208x; 1.0138x over previous
#include <cuda_runtime.h>
#include <cuda_fp16.h>
#include <cstdint>
#include <cstddef>

#define NE 2048
#define NH 16
#define HD 128
#define SB 2048
#define NB 2
#define MT 4096     // NB*SB
#define NQKV 2304   // 2048 (Q) + 128 (K) + 128 (V)

// ---------------- scratch (__device__ globals; no allocs) ------------------
__device__ __half g_xh   [MT * NE];
__device__ __half g_qkvh [MT * NQKV];      // fused Q|K|V, row stride 2304
__device__ __half g_aoh  [MT * NE];
__device__ __half g_wqkvh[NQKV * NE];
__device__ __half g_woh  [NE * NE];
__device__ float  g_bqkv [NQKV];

// ---------------- PTX helpers (sm_80-safe; no 'a' features) ----------------
#define CP16(sa, g)  asm volatile("cp.async.cg.shared.global [%0], [%1], 16;" :: "r"(sa), "l"(g))
#define CP_COMMIT()  asm volatile("cp.async.commit_group;" ::: "memory")
#define CP_WAIT1()   asm volatile("cp.async.wait_group 1;" ::: "memory")
#define CP_WAIT0()   asm volatile("cp.async.wait_group 0;" ::: "memory")

#define LDSM_X4(r0,r1,r2,r3, addr) \
    asm volatile("ldmatrix.sync.aligned.m8n8.x4.shared.b16 {%0,%1,%2,%3}, [%4];" \
        : "=r"(r0),"=r"(r1),"=r"(r2),"=r"(r3) : "r"(addr))
#define LDSM_X4T(r0,r1,r2,r3, addr) \
    asm volatile("ldmatrix.sync.aligned.m8n8.x4.trans.shared.b16 {%0,%1,%2,%3}, [%4];" \
        : "=r"(r0),"=r"(r1),"=r"(r2),"=r"(r3) : "r"(addr))
#define LDSM_X2T(r0,r1, addr) \
    asm volatile("ldmatrix.sync.aligned.m8n8.x2.trans.shared.b16 {%0,%1}, [%2];" \
        : "=r"(r0),"=r"(r1) : "r"(addr))
#define MMA16816(c0,c1,c2,c3, a0,a1,a2,a3, b0,b1) \
    asm volatile("mma.sync.aligned.m16n8k16.row.col.f32.f16.f16.f32 " \
        "{%0,%1,%2,%3}, {%4,%5,%6,%7}, {%8,%9}, {%0,%1,%2,%3};" \
        : "+f"(c0),"+f"(c1),"+f"(c2),"+f"(c3) \
        : "r"(a0),"r"(a1),"r"(a2),"r"(a3),"r"(b0),"r"(b1))
#define EX2H2(x) asm volatile("ex2.approx.f16x2 %0, %0;" : "+r"(x))

__device__ __forceinline__ uint32_t smem_u32(const void* p) {
    return (uint32_t)__cvta_generic_to_shared(p);
}
__device__ __forceinline__ uint32_t pack_h2(float a, float b) {
    __half2 h = __floats2half2_rn(a, b);
    return *(uint32_t*)&h;
}
__device__ __forceinline__ float ex2f(float x) {
    float y;
    asm("ex2.approx.ftz.f32 %0, %1;" : "=f"(y) : "f"(x));
    return y;
}

// ---------------- fused conversion kernels ----------------------------------
__global__ void __launch_bounds__(256)
conv_wb(const float* __restrict__ Wq, const float* __restrict__ Wk,
        const float* __restrict__ Wv, const float* __restrict__ Wo,
        const float* __restrict__ bq, const float* __restrict__ bk,
        const float* __restrict__ bv,
        __half* __restrict__ wqkvh, __half* __restrict__ woh,
        float* __restrict__ bqkv, float scale)
{
    constexpr int S0 = NE * NE;
    constexpr int S1 = S0 + HD * NE;
    constexpr int S2 = S1 + HD * NE;
    constexpr int S3 = S2 + NE * NE;
    const int i = (blockIdx.x * 256 + threadIdx.x) * 4;
    if (i < S0) {
        float4 v = *(const float4*)(Wq + i);
        __half2* o = (__half2*)(wqkvh + i);
        o[0] = __floats2half2_rn(v.x * scale, v.y * scale);
        o[1] = __floats2half2_rn(v.z * scale, v.w * scale);
    } else if (i < S1) {
        const int j = i - S0;
        float4 v = *(const float4*)(Wk + j);
        __half2* o = (__half2*)(wqkvh + NE * NE + j);
        o[0] = __floats2half2_rn(v.x, v.y);
        o[1] = __floats2half2_rn(v.z, v.w);
    } else if (i < S2) {
        const int j = i - S1;
        float4 v = *(const float4*)(Wv + j);
        __half2* o = (__half2*)(wqkvh + (NE + HD) * NE + j);
        o[0] = __floats2half2_rn(v.x, v.y);
        o[1] = __floats2half2_rn(v.z, v.w);
    } else if (i < S3) {
        const int j = i - S2;
        float4 v = *(const float4*)(Wo + j);
        __half2* o = (__half2*)(woh + j);
        o[0] = __floats2half2_rn(v.x, v.y);
        o[1] = __floats2half2_rn(v.z, v.w);
    } else {
        #pragma unroll
        for (int u = 0; u < 4; u++) {
            const int bidx = (i - S3) + u;
            if (bidx < NE)            bqkv[bidx] = bq[bidx] * scale;
            else if (bidx < NE + HD)  bqkv[bidx] = bk[bidx - NE];
            else if (bidx < NQKV)     bqkv[bidx] = bv[bidx - NE - HD];
        }
    }
}

__global__ void __launch_bounds__(256)
conv_x(const float* __restrict__ in, __half* __restrict__ out, int n)
{
    int i = (blockIdx.x * 256 + threadIdx.x) * 4;
    if (i < n) {
        float4 v = *(const float4*)(in + i);
        __half2* o = (__half2*)(out + i);
        o[0] = __floats2half2_rn(v.x, v.y);
        o[1] = __floats2half2_rn(v.z, v.w);
    }
}

// ---------------------------------------------------------------------------
// HMMA GEMM: 128x128 CTA tile, 4 warps, warp tile 64x64, BK=32,
// 3-stage cp.async, 2 CTAs/SM. (R7/R9-validated)
// ---------------------------------------------------------------------------
#define PAD 40
#define STG (128 * PAD)
#define AOFF(st) ((st) * STG * 2)
#define BOFF(st) (3 * STG * 2 + (st) * STG * 2)
#define GEMM_SMEM (6 * STG * 2)

template<typename OutT>
__global__ void __launch_bounds__(128, 2)
gemm_hmma64(const __half* __restrict__ A, const __half* __restrict__ B,
            const float* __restrict__ bias, OutT* __restrict__ C,
            int M, int N, int K)
{
    extern __shared__ __half sh[];
    const uint32_t smb = smem_u32(sh);

    const int tid  = threadIdx.x;
    const int wid  = tid >> 5;
    const int lane = tid & 31;
    const int bm = blockIdx.y * 128;
    const int bn = blockIdx.x * 128;
    const int m0 = (wid >> 1) * 64;
    const int n0 = (wid & 1) * 64;

    const int lrow = tid >> 2;
    const int lch  = tid & 3;

    float c[4][8][4];
    #pragma unroll
    for (int mt = 0; mt < 4; mt++)
        #pragma unroll
        for (int nt = 0; nt < 8; nt++)
            #pragma unroll
            for (int r = 0; r < 4; r++) c[mt][nt][r] = 0.f;

    const __half* Ab = A + (size_t)bm * K;
    const __half* Bb = B + (size_t)bn * K;
    const int nk = K / 32;

    auto load_stage = [&](int st, int k0) {
        #pragma unroll
        for (int r = 0; r < 4; r++) {
            const int row = lrow + r * 32;
            const uint32_t so = (uint32_t)(row * PAD + lch * 8) * 2;
            CP16(smb + AOFF(st) + so, Ab + (size_t)row * K + k0 + lch * 8);
            CP16(smb + BOFF(st) + so, Bb + (size_t)row * K + k0 + lch * 8);
        }
    };

    load_stage(0, 0);  CP_COMMIT();
    load_stage(1, 32); CP_COMMIT();

    const int a_r = lane & 15, a_c = (lane >> 4) * 8;
    const int b_row = ((lane >> 4) << 3) + (lane & 7);
    const int b_col = ((lane >> 3) & 1) * 8;

    for (int i = 0; i < nk; i++) {
        CP_WAIT1();
        __syncthreads();
        if (i + 2 < nk) load_stage((i + 2) % 3, (i + 2) * 32);
        CP_COMMIT();

        const int st = i % 3;
        #pragma unroll
        for (int ks = 0; ks < 2; ks++) {
            uint32_t a[4][4], b[8][2];
            #pragma unroll
            for (int mt = 0; mt < 4; mt++) {
                const uint32_t addr = smb + AOFF(st) +
                    (uint32_t)((m0 + mt * 16 + a_r) * PAD + ks * 16 + a_c) * 2;
                LDSM_X4(a[mt][0], a[mt][1], a[mt][2], a[mt][3], addr);
            }
            #pragma unroll
            for (int np = 0; np < 4; np++) {
                const uint32_t addr = smb + BOFF(st) +
                    (uint32_t)((n0 + np * 16 + b_row) * PAD + ks * 16 + b_col) * 2;
                LDSM_X4(b[2*np][0], b[2*np][1], b[2*np+1][0], b[2*np+1][1], addr);
            }
            #pragma unroll
            for (int mt = 0; mt < 4; mt++)
                #pragma unroll
                for (int nt = 0; nt < 8; nt++)
                    MMA16816(c[mt][nt][0], c[mt][nt][1], c[mt][nt][2], c[mt][nt][3],
                             a[mt][0], a[mt][1], a[mt][2], a[mt][3],
                             b[nt][0], b[nt][1]);
        }
        __syncthreads();
    }

    const int tr  = lane >> 2;
    const int tc2 = (lane & 3) * 2;
    #pragma unroll
    for (int mt = 0; mt < 4; mt++) {
        const int r0 = bm + m0 + mt * 16 + tr;
        #pragma unroll
        for (int nt = 0; nt < 8; nt++) {
            const int cc = bn + n0 + nt * 8 + tc2;
            const float bx = bias[cc], by = bias[cc + 1];
            if constexpr (sizeof(OutT) == 4) {
                *(float2*)&C[(size_t)r0 * N + cc] =
                    make_float2(c[mt][nt][0] + bx, c[mt][nt][1] + by);
                *(float2*)&C[(size_t)(r0 + 8) * N + cc] =
                    make_float2(c[mt][nt][2] + bx, c[mt][nt][3] + by);
            } else {
                *(__half2*)&C[(size_t)r0 * N + cc] =
                    __floats2half2_rn(c[mt][nt][0] + bx, c[mt][nt][1] + by);
                *(__half2*)&C[(size_t)(r0 + 8) * N + cc] =
                    __floats2half2_rn(c[mt][nt][2] + bx, c[mt][nt][3] + by);
            }
        }
    }
}

// ---------------------------------------------------------------------------
// HMMA MQA flash attention v7: 64 q-rows/CTA, 4 warps x 16 rows, 32-col KV
// tiles, 2 smem KV buffers. LATENCY FIX (R14 post-mortem): Q fragments
// preloaded ONCE into registers; K and V fragments register-double-buffered
// so every MMA consumes fragments LDSMed a full iteration earlier -- breaks
// the LDSM->MMA ~29cyc dependency stalls that pinned issue at 33%.
// ---------------------------------------------------------------------------
#define QROWS 64
#define QSM   8704u                           // Q halves (64 x 136)
#define KVT   32                              // kv tile rows
#define KHALF 4352u                           // one K (or V) tile halves
#define KVSM  (2u * KHALF)                    // one KV buffer (K+V)
#define ATT_SMEM ((QSM + 2u * KVSM) * 2u)     // 52224 B

__global__ void __launch_bounds__(128)
mqa_attn_h(const __half* __restrict__ qkv, __half* __restrict__ ao)
{
    extern __shared__ __half sh[];
    const uint32_t smb = smem_u32(sh);

    const int tid = threadIdx.x, wid = tid >> 5, lane = tid & 31;
    const int qt = gridDim.x - 1 - blockIdx.x;     // heavy tiles first
    const int h = blockIdx.y, b = blockIdx.z;
    const int q0 = qt * QROWS;
    const int ntk = 2 * qt + 2;                    // 32-wide kv tiles
    const int gid = lane >> 2, tig = lane & 3;
    const int m0w = wid * 16;

    // ---- Q tile load ----
    {
        const __half* qg = qkv + (size_t)(b * SB + q0) * NQKV + h * HD;
        #pragma unroll
        for (int i = 0; i < 8; i++) {
            const int c = i * 128 + tid;
            const int row = c >> 4, ch = c & 15;
            CP16(smb + (uint32_t)(row * 136 + ch * 8) * 2,
                 qg + (size_t)row * NQKV + ch * 8);
        }
    }
    CP_COMMIT();

    auto load_kv = [&](int jt, int buf) {
        const __half* g = qkv + (size_t)(b * SB + jt * KVT) * NQKV + NE;
        const uint32_t kb = QSM + (uint32_t)buf * KVSM;
        #pragma unroll
        for (int i = 0; i < 8; i++) {
            const int c = i * 128 + tid;
            const int row = c >> 5, ch = c & 31;
            const uint32_t off = kb + ((ch & 16) ? KHALF : 0u)
                               + (uint32_t)(row * 136 + (ch & 15) * 8);
            CP16(smb + off * 2, g + (size_t)row * NQKV + ch * 8);
        }
    };
    load_kv(0, 0);
    CP_COMMIT();

    // ones-column in V pad (cols 128..135), both buffers, written once
    if (tid < KVT) {
        uint4 onev = make_uint4(0x00003C00u, 0u, 0u, 0u);
        *(uint4*)(sh + QSM + KHALF + (uint32_t)tid * 136u + 128u) = onev;
        *(uint4*)(sh + QSM + KVSM + KHALF + (uint32_t)tid * 136u + 128u) = onev;
    }
    CP_WAIT0();
    __syncthreads();

    const int a_r = lane & 15, a_c = (lane >> 4) * 8;
    const int k_row = ((lane >> 4) << 3) + (lane & 7);
    const int k_col = ((lane >> 3) & 1) * 8;
    const int v_row = ((lane >> 3) & 1) * 8 + (lane & 7);
    const int v_col = (lane >> 4) * 8;

    // ---- preload Q fragments ONCE (invariant across all KV tiles) ----
    uint32_t qa[8][4];
    #pragma unroll
    for (int kt = 0; kt < 8; kt++)
        LDSM_X4(qa[kt][0], qa[kt][1], qa[kt][2], qa[kt][3], smb +
            (uint32_t)((m0w + a_r) * 136 + kt * 16 + a_c) * 2);

    float co[16][4];
    float cl[4];
    #pragma unroll
    for (int n = 0; n < 16; n++)
        #pragma unroll
        for (int r = 0; r < 4; r++) co[n][r] = 0.f;
    #pragma unroll
    for (int r = 0; r < 4; r++) cl[r] = 0.f;
    float m0r = -1e30f, m1r = -1e30f;

    for (int jt = 0; jt < ntk; jt++) {
        if (jt > 0) { CP_WAIT0(); __syncthreads(); }
        if (jt + 1 < ntk) { load_kv(jt + 1, (jt + 1) & 1); CP_COMMIT(); }

        const int buf = jt & 1;
        const uint32_t kbB = smb + (QSM + (uint32_t)buf * KVSM) * 2u;
        const uint32_t vbB = kbB + KHALF * 2u;

        // ---- S = Q K^T, K frags register-double-buffered over kt ----
        float s[4][4];
        #pragma unroll
        for (int n = 0; n < 4; n++)
            #pragma unroll
            for (int r = 0; r < 4; r++) s[n][r] = 0.f;

        uint32_t kf[2][2][4];   // [pipe buf][np][frag]
        #pragma unroll
        for (int np = 0; np < 2; np++)
            LDSM_X4(kf[0][np][0], kf[0][np][1], kf[0][np][2], kf[0][np][3],
                kbB + (uint32_t)((np * 16 + k_row) * 136 + k_col) * 2);

        #pragma unroll
        for (int kt = 0; kt < 8; kt++) {
            const int cur = kt & 1, nxt = cur ^ 1;
            if (kt < 7) {
                #pragma unroll
                for (int np = 0; np < 2; np++)
                    LDSM_X4(kf[nxt][np][0], kf[nxt][np][1],
                            kf[nxt][np][2], kf[nxt][np][3],
                        kbB + (uint32_t)((np * 16 + k_row) * 136
                                         + (kt + 1) * 16 + k_col) * 2);
            }
            #pragma unroll
            for (int np = 0; np < 2; np++) {
                MMA16816(s[2*np][0], s[2*np][1], s[2*np][2], s[2*np][3],
                         qa[kt][0], qa[kt][1], qa[kt][2], qa[kt][3],
                         kf[cur][np][0], kf[cur][np][1]);
                MMA16816(s[2*np+1][0], s[2*np+1][1], s[2*np+1][2], s[2*np+1][3],
                         qa[kt][0], qa[kt][1], qa[kt][2], qa[kt][3],
                         kf[cur][np][2], kf[cur][np][3]);
            }
        }

        // ---- causal mask (last 2 tiles straddle the diagonal) ----
        if (jt >= ntk - 2) {
            const int rg0 = q0 + m0w + gid;
            const int rg1 = rg0 + 8;
            #pragma unroll
            for (int nt = 0; nt < 4; nt++) {
                const int cg0 = jt * KVT + nt * 8 + tig * 2;
                const int cg1 = cg0 + 1;
                if (cg0 > rg0) s[nt][0] = -1e30f;
                if (cg1 > rg0) s[nt][1] = -1e30f;
                if (cg0 > rg1) s[nt][2] = -1e30f;
                if (cg1 > rg1) s[nt][3] = -1e30f;
            }
        }

        // ---- online softmax (log2 domain, packed ex2) ----
        float mx0 = -1e30f, mx1 = -1e30f;
        #pragma unroll
        for (int nt = 0; nt < 4; nt++) {
            mx0 = fmaxf(mx0, fmaxf(s[nt][0], s[nt][1]));
            mx1 = fmaxf(mx1, fmaxf(s[nt][2], s[nt][3]));
        }
        mx0 = fmaxf(mx0, __shfl_xor_sync(0xffffffffu, mx0, 1));
        mx0 = fmaxf(mx0, __shfl_xor_sync(0xffffffffu, mx0, 2));
        mx1 = fmaxf(mx1, __shfl_xor_sync(0xffffffffu, mx1, 1));
        mx1 = fmaxf(mx1, __shfl_xor_sync(0xffffffffu, mx1, 2));

        const float mn0 = fmaxf(m0r, mx0);
        const float mn1 = fmaxf(m1r, mx1);
        const float al0 = ex2f(m0r - mn0);
        const float al1 = ex2f(m1r - mn1);
        m0r = mn0;
        m1r = mn1;

        uint32_t pa[2][4];
        #pragma unroll
        for (int nt = 0; nt < 4; nt++) {
            uint32_t p0 = pack_h2(s[nt][0] - mn0, s[nt][1] - mn0);
            uint32_t p1 = pack_h2(s[nt][2] - mn1, s[nt][3] - mn1);
            EX2H2(p0);
            EX2H2(p1);
            pa[nt >> 1][(nt & 1) * 2]     = p0;
            pa[nt >> 1][(nt & 1) * 2 + 1] = p1;
        }

        #pragma unroll
        for (int nt = 0; nt < 16; nt++) {
            co[nt][0] *= al0; co[nt][1] *= al0;
            co[nt][2] *= al1; co[nt][3] *= al1;
        }
        cl[0] *= al0; cl[1] *= al0;
        cl[2] *= al1; cl[3] *= al1;

        // ---- O += P V ; V frags register-double-buffered over (t,dp) ----
        uint32_t vf[2][4];
        LDSM_X4T(vf[0][0], vf[0][1], vf[0][2], vf[0][3],
                 vbB + (uint32_t)(v_row * 136 + v_col) * 2);
        #pragma unroll
        for (int i = 0; i < 16; i++) {          // i = t*8 + dp
            const int t  = i >> 3, dp = i & 7;
            const int cur = i & 1, nxt = cur ^ 1;
            if (i < 15) {
                const int tn  = (i + 1) >> 3, dpn = (i + 1) & 7;
                LDSM_X4T(vf[nxt][0], vf[nxt][1], vf[nxt][2], vf[nxt][3],
                    vbB + (uint32_t)((tn * 16 + v_row) * 136
                                     + dpn * 16 + v_col) * 2);
            }
            MMA16816(co[2*dp][0], co[2*dp][1], co[2*dp][2], co[2*dp][3],
                     pa[t][0], pa[t][1], pa[t][2], pa[t][3],
                     vf[cur][0], vf[cur][1]);
            MMA16816(co[2*dp+1][0], co[2*dp+1][1], co[2*dp+1][2], co[2*dp+1][3],
                     pa[t][0], pa[t][1], pa[t][2], pa[t][3],
                     vf[cur][2], vf[cur][3]);
        }
        // ones-column (row-sum l)
        #pragma unroll
        for (int t = 0; t < 2; t++) {
            uint32_t e0, e1;
            LDSM_X2T(e0, e1, vbB + (uint32_t)(
                (t * 16 + v_row) * 136 + 128) * 2);
            MMA16816(cl[0], cl[1], cl[2], cl[3],
                     pa[t][0], pa[t][1], pa[t][2], pa[t][3], e0, e1);
        }
    }

    // ---- finalize ----
    const float l0 = __shfl_sync(0xffffffffu, cl[0], lane & 28);
    const float l1 = __shfl_sync(0xffffffffu, cl[2], lane & 28);
    const float inv0 = 1.f / l0, inv1 = 1.f / l1;
    const int r0 = q0 + m0w + gid, r1 = r0 + 8;
    __half* o0 = ao + (size_t)(b * SB + r0) * NE + h * HD;
    __half* o1 = ao + (size_t)(b * SB + r1) * NE + h * HD;
    #pragma unroll
    for (int nt = 0; nt < 16; nt++) {
        const int cc = nt * 8 + tig * 2;
        *(__half2*)(o0 + cc) = __floats2half2_rn(co[nt][0] * inv0,
                                                 co[nt][1] * inv0);
        *(__half2*)(o1 + cc) = __floats2half2_rn(co[nt][2] * inv1,
                                                 co[nt][3] * inv1);
    }
}

// ---------------------------------------------------------------------------
extern "C" void kernel_launch(void* const* d_in, const int* in_sizes, int n_in,
                              void* d_out, int out_size)
{
    const float* x  = (const float*)d_in[0];
    const float* Wq = (const float*)d_in[1];
    const float* bq = (const float*)d_in[2];
    const float* Wk = (const float*)d_in[3];
    const float* bk = (const float*)d_in[4];
    const float* Wv = (const float*)d_in[5];
    const float* bv = (const float*)d_in[6];
    const float* Wo = (const float*)d_in[7];
    const float* bo = (const float*)d_in[8];
    float* out = (float*)d_out;

    __half *xh, *qkvh, *aoh, *wqkvh, *woh;
    float *bqkv;
    cudaGetSymbolAddress((void**)&xh,    g_xh);
    cudaGetSymbolAddress((void**)&qkvh,  g_qkvh);
    cudaGetSymbolAddress((void**)&aoh,   g_aoh);
    cudaGetSymbolAddress((void**)&wqkvh, g_wqkvh);
    cudaGetSymbolAddress((void**)&woh,   g_woh);
    cudaGetSymbolAddress((void**)&bqkv,  g_bqkv);

    cudaFuncSetAttribute(gemm_hmma64<__half>, cudaFuncAttributeMaxDynamicSharedMemorySize, GEMM_SMEM);
    cudaFuncSetAttribute(gemm_hmma64<float>,  cudaFuncAttributeMaxDynamicSharedMemorySize, GEMM_SMEM);
    cudaFuncSetAttribute(mqa_attn_h, cudaFuncAttributeMaxDynamicSharedMemorySize, ATT_SMEM);

    // 1/sqrt(128) * log2(e): logits in log2 domain
    const float scale = 0.08838834764831845f * 1.4426950408889634f;
    dim3 cblk(256);

    constexpr int WTOT = NQKV * NE + NE * NE;
    constexpr int GRID1 = (WTOT + NQKV * 4 + 1023) / 1024;
    conv_wb<<<GRID1, cblk>>>(Wq, Wk, Wv, Wo, bq, bk, bv, wqkvh, woh, bqkv, scale);
    conv_x<<<(MT * NE) / 1024, cblk>>>(x, xh, MT * NE);

    gemm_hmma64<__half><<<dim3(NQKV / 128, MT / 128), dim3(128), GEMM_SMEM>>>(
        xh, wqkvh, bqkv, qkvh, MT, NQKV, NE);
    // launch 4: attention (profiled slot)
    mqa_attn_h<<<dim3(SB / QROWS, NH, NB), dim3(128), ATT_SMEM>>>(qkvh, aoh);
    gemm_hmma64<float><<<dim3(NE / 128, MT / 128), dim3(128), GEMM_SMEM>>>(
        aoh, woh, bo, out, MT, NE, NE);
}